// round 11
// baseline (speedup 1.0000x reference)
#include <cuda_runtime.h>
#include <cuda_fp16.h>

// ---------------- problem constants ----------------
#define GG   33
#define G3   35937            // 33^3
#define KK   8
#define RR   8
#define NB   4
#define HL   256
#define WL   256
#define HF   1080
#define WF   1920
#define NPIX (HF*WF)          // 2,073,600
#define OUT_IMG (NB*3*NPIX)   // 24,883,200

// d_out layout: out | alpha | delta | L | delta_norm  (all float32, concatenated)
#define ALPHA_OFF OUT_IMG
#define DELTA_SZ  (NB*G3*3)            // 431,244
#define DELTA_OFF (ALPHA_OFF + 32)
#define L_OFF     (DELTA_OFF + DELTA_SZ)
#define NORM_OFF  (L_OFF + DELTA_SZ)

#define TRI_SMEM (G3*4 + 16)           // packed uint32 LUT: 143.7 KB

// ---------------- device scratch (no allocations allowed) ----------------
__device__ float g_s1[2*NB*16*128*128];   // conv1 outputs, both encoders
__device__ float g_hsum[2*NB*32];
__device__ float g_A[NB];                 // sum_k alpha[b][k]  (ramp slope)
__device__ float g_norm;
__device__ unsigned int g_rmin[3];        // mapped-uint residual min per channel
__device__ unsigned int g_rmax[3];

// monotonic float<->uint mapping for atomic min/max
__device__ __forceinline__ unsigned int fmap(float f) {
    unsigned int b = __float_as_uint(f);
    return b ^ (((unsigned int)((int)b >> 31)) | 0x80000000u);
}
__device__ __forceinline__ float funmap(unsigned int m) {
    unsigned int b = (m & 0x80000000u) ? (m ^ 0x80000000u) : ~m;
    return __uint_as_float(b);
}

// ============================================================
// K1: conv1 (3->16, 3x3, stride2, pad1) + relu, both encoders
// blk 0 also initializes the global reduction scalars.
// ============================================================
__global__ void __launch_bounds__(256) conv1_kernel(
    const float* __restrict__ img_lr,
    const float* __restrict__ w_wp, const float* __restrict__ b_wp,
    const float* __restrict__ w_rp, const float* __restrict__ b_rp)
{
    __shared__ float ws[432];
    __shared__ float bs[16];
    int blk = blockIdx.x;          // 0..511
    int e   = blk >> 8;
    int rem = blk & 255;
    int b   = rem >> 6;
    int tile= rem & 63;
    const float* w  = e ? w_rp : w_wp;
    const float* bi = e ? b_rp : b_wp;
    int tid = threadIdx.x;
    for (int i = tid; i < 432; i += 256) ws[i] = w[i];
    if (tid < 16) bs[tid] = bi[tid];
    if (blk == 0) {
        g_hsum[tid] = 0.f;
        if (tid == 0) g_norm = 0.f;
        if (tid < 3) { g_rmin[tid] = 0xFFFFFFFFu; g_rmax[tid] = 0u; }
    }
    __syncthreads();

    int pix = tile*256 + tid;
    int oh = pix >> 7, ow = pix & 127;
    float in[27];
    #pragma unroll
    for (int ci = 0; ci < 3; ci++)
      #pragma unroll
      for (int kh = 0; kh < 3; kh++)
        #pragma unroll
        for (int kw = 0; kw < 3; kw++) {
            int ih = 2*oh - 1 + kh, iw = 2*ow - 1 + kw;
            float v = 0.f;
            if (ih >= 0 && ih < HL && iw >= 0 && iw < WL)
                v = img_lr[((b*3 + ci)*HL + ih)*WL + iw];
            in[ci*9 + kh*3 + kw] = v;
        }
    float acc[16];
    #pragma unroll
    for (int co = 0; co < 16; co++) acc[co] = bs[co];
    #pragma unroll
    for (int j = 0; j < 27; j++) {
        float v = in[j];
        #pragma unroll
        for (int co = 0; co < 16; co++) acc[co] = fmaf(v, ws[co*27 + j], acc[co]);
    }
    float* outp = g_s1 + (size_t)(e*NB + b)*16*16384 + pix;
    #pragma unroll
    for (int co = 0; co < 16; co++) outp[co*16384] = fmaxf(acc[co], 0.f);
}

// ============================================================
// K2: conv2 (16->32, 3x3, stride2, pad1) + relu + spatial-sum
// ============================================================
__global__ void __launch_bounds__(256) conv2_kernel(
    const float* __restrict__ w_wp, const float* __restrict__ b_wp,
    const float* __restrict__ w_rp, const float* __restrict__ b_rp)
{
    __shared__ float ws[2304];   // [(ci*9+k)*16 + co_local]
    __shared__ float bs[16];
    __shared__ float red[8*16];
    int blk = blockIdx.x;        // 0..255
    int e      = blk >> 7;
    int rem    = blk & 127;
    int b      = rem >> 5;
    int cohalf = (rem >> 4) & 1;
    int tile   = rem & 15;
    const float* w  = e ? w_rp : w_wp;
    const float* bi = e ? b_rp : b_wp;
    int tid = threadIdx.x;
    for (int t = tid; t < 2304; t += 256) {
        int col = t & 15;
        int cik = t >> 4;
        int ci = cik / 9, k = cik - ci*9;
        ws[t] = w[((cohalf*16 + col)*16 + ci)*9 + k];
    }
    if (tid < 16) bs[tid] = bi[cohalf*16 + tid];
    __syncthreads();

    int pix = tile*256 + tid;
    int oh = pix >> 6, ow = pix & 63;
    const float* inp = g_s1 + (size_t)(e*NB + b)*16*16384;
    float acc[16];
    #pragma unroll
    for (int co = 0; co < 16; co++) acc[co] = 0.f;
    for (int ci = 0; ci < 16; ci++) {
        float v9[9];
        #pragma unroll
        for (int kh = 0; kh < 3; kh++)
          #pragma unroll
          for (int kw = 0; kw < 3; kw++) {
              int ih = 2*oh - 1 + kh, iw = 2*ow - 1 + kw;
              float v = 0.f;
              if (ih >= 0 && ih < 128 && iw >= 0 && iw < 128)
                  v = inp[ci*16384 + ih*128 + iw];
              v9[kh*3 + kw] = v;
          }
        #pragma unroll
        for (int k = 0; k < 9; k++) {
            float v = v9[k];
            const float* wrow = &ws[(ci*9 + k)*16];
            #pragma unroll
            for (int co = 0; co < 16; co++) acc[co] = fmaf(v, wrow[co], acc[co]);
        }
    }
    int lane = tid & 31, wid = tid >> 5;
    #pragma unroll
    for (int co = 0; co < 16; co++) {
        float v = fmaxf(acc[co] + bs[co], 0.f);   // relu BEFORE mean
        v += __shfl_down_sync(0xffffffffu, v, 16);
        v += __shfl_down_sync(0xffffffffu, v, 8);
        v += __shfl_down_sync(0xffffffffu, v, 4);
        v += __shfl_down_sync(0xffffffffu, v, 2);
        v += __shfl_down_sync(0xffffffffu, v, 1);
        if (lane == 0) red[wid*16 + co] = v;
    }
    __syncthreads();
    if (tid < 16) {
        float s = 0.f;
        #pragma unroll
        for (int w8 = 0; w8 < 8; w8++) s += red[w8*16 + tid];
        atomicAdd(&g_hsum[(e*NB + b)*32 + cohalf*16 + tid], s);
    }
}

// ============================================================
// K3: delta + L + residual min/max, with the FC heads computed
// redundantly per block in the prologue (fc_kernel eliminated).
// 4 batches per thread: bases[k][n][:] loaded once, reused x4.
// ============================================================
__global__ void __launch_bounds__(256) delta_kernel(
    const float* __restrict__ bases, float* __restrict__ d_out,
    const float* __restrict__ wp_fc_w, const float* __restrict__ wp_fc_b,
    const float* __restrict__ fcu_w,  const float* __restrict__ fcu_b,
    const float* __restrict__ fcv_w,  const float* __restrict__ fcv_b,
    const float* __restrict__ fcw_w,  const float* __restrict__ fcw_b,
    const float* __restrict__ fcc_w,  const float* __restrict__ fcc_b)
{
    __shared__ float h[2*NB*32];
    __shared__ float su[NB*RR*GG], sv[NB*RR*GG], sw[NB*RR*GG];
    __shared__ float sc[NB*RR*3];
    __shared__ float sa[NB*KK];
    __shared__ float sA[NB];
    int tid = threadIdx.x;

    // ---- FC prologue (every block; weights are L2-resident) ----
    h[tid] = g_hsum[tid] * (1.f/4096.f);
    __syncthreads();
    if (tid < NB*KK) {                        // alpha (wp encoder)
        int b = tid >> 3, k = tid & 7;
        float s = wp_fc_b[k];
        const float* hb = &h[b*32];
        #pragma unroll
        for (int i = 0; i < 32; i++) s = fmaf(hb[i], wp_fc_w[k*32 + i], s);
        sa[tid] = s;
        if (blockIdx.x == 0) d_out[ALPHA_OFF + tid] = s;
    }
    __syncthreads();
    if (tid < NB) {
        float a = 0.f;
        #pragma unroll
        for (int k = 0; k < KK; k++) a += sa[tid*KK + k];
        sA[tid] = a;
        if (blockIdx.x == 0) g_A[tid] = a;
    }
    for (int j = tid; j < NB*RR*GG; j += 256) {   // u,v,w (rp encoder)
        int b = j / (RR*GG), jj = j - b*(RR*GG);
        const float* hb = &h[(NB + b)*32];
        float vu = fcu_b[jj], vv = fcv_b[jj], vw = fcw_b[jj];
        #pragma unroll
        for (int i = 0; i < 32; i++) {
            float hv = hb[i];
            vu = fmaf(hv, fcu_w[jj*32 + i], vu);
            vv = fmaf(hv, fcv_w[jj*32 + i], vv);
            vw = fmaf(hv, fcw_w[jj*32 + i], vw);
        }
        su[j] = vu; sv[j] = vv; sw[j] = vw;
    }
    for (int j = tid; j < NB*RR*3; j += 256) {    // c
        int b = j / (RR*3), jj = j - b*(RR*3);
        const float* hb = &h[(NB + b)*32];
        float s = fcc_b[jj];
        #pragma unroll
        for (int i = 0; i < 32; i++) s = fmaf(hb[i], fcc_w[jj*32 + i], s);
        sc[j] = s;
    }
    __syncthreads();

    // ---- main delta/L body ----
    int n = blockIdx.x*256 + tid;
    float local = 0.f;
    unsigned int mn0 = 0xFFFFFFFFu, mn1 = 0xFFFFFFFFu, mn2 = 0xFFFFFFFFu;
    unsigned int mx0 = 0u, mx1 = 0u, mx2 = 0u;
    if (n < G3) {
        int x = n / 1089, rem = n - x*1089;
        int y = rem / 33, z = rem - y*33;
        float bb[KK][3];
        #pragma unroll
        for (int k = 0; k < KK; k++) {
            const float* bp = bases + ((size_t)k*G3 + n)*3;
            bb[k][0] = bp[0]; bb[k][1] = bp[1]; bb[k][2] = bp[2];
        }
        #pragma unroll
        for (int b = 0; b < NB; b++) {
            float d0 = 0.f, d1 = 0.f, d2 = 0.f;
            #pragma unroll
            for (int r = 0; r < RR; r++) {
                int o = b*RR + r;
                float p = su[o*GG + x] * sv[o*GG + y] * sw[o*GG + z];
                d0 = fmaf(p, sc[o*3 + 0], d0);
                d1 = fmaf(p, sc[o*3 + 1], d1);
                d2 = fmaf(p, sc[o*3 + 2], d2);
            }
            float l0 = d0, l1 = d1, l2 = d2;
            #pragma unroll
            for (int k = 0; k < KK; k++) {
                float a = sa[b*KK + k];
                l0 = fmaf(a, bb[k][0], l0);
                l1 = fmaf(a, bb[k][1], l1);
                l2 = fmaf(a, bb[k][2], l2);
            }
            size_t off = (size_t)(b*G3 + n)*3;
            d_out[DELTA_OFF + off    ] = d0;
            d_out[DELTA_OFF + off + 1] = d1;
            d_out[DELTA_OFF + off + 2] = d2;
            d_out[L_OFF + off    ] = l0;
            d_out[L_OFF + off + 1] = l1;
            d_out[L_OFF + off + 2] = l2;
            local += fabsf(d0) + fabsf(d1) + fabsf(d2);
            float a32 = sA[b] * (1.f/32.f);
            unsigned int r0 = fmap(l0 - a32*(float)x);
            unsigned int r1 = fmap(l1 - a32*(float)y);
            unsigned int r2 = fmap(l2 - a32*(float)z);
            mn0 = min(mn0, r0); mx0 = max(mx0, r0);
            mn1 = min(mn1, r1); mx1 = max(mx1, r1);
            mn2 = min(mn2, r2); mx2 = max(mx2, r2);
        }
    }
    mn0 = __reduce_min_sync(0xffffffffu, mn0);
    mn1 = __reduce_min_sync(0xffffffffu, mn1);
    mn2 = __reduce_min_sync(0xffffffffu, mn2);
    mx0 = __reduce_max_sync(0xffffffffu, mx0);
    mx1 = __reduce_max_sync(0xffffffffu, mx1);
    mx2 = __reduce_max_sync(0xffffffffu, mx2);
    local += __shfl_down_sync(0xffffffffu, local, 16);
    local += __shfl_down_sync(0xffffffffu, local, 8);
    local += __shfl_down_sync(0xffffffffu, local, 4);
    local += __shfl_down_sync(0xffffffffu, local, 2);
    local += __shfl_down_sync(0xffffffffu, local, 1);
    if ((threadIdx.x & 31) == 0) {
        atomicAdd(&g_norm, local);
        atomicMin(&g_rmin[0], mn0); atomicMax(&g_rmax[0], mx0);
        atomicMin(&g_rmin[1], mn1); atomicMax(&g_rmax[1], mx1);
        atomicMin(&g_rmin[2], mn2); atomicMax(&g_rmax[2], mx2);
    }
}

// ============================================================
// K4: trilinear LUT apply. Packed 11/11/10 smem LUT (quantize fused
// into fill). Scalar math, magic-number floor (no CVT), 2px/iter.
// ============================================================
struct QP { float s0, s1, s2, l0, l1, l2, A; };

__device__ __forceinline__ void lut1(
    float r, float g, float bv,
    const unsigned int* __restrict__ sm, const QP& qp,
    float& o0, float& o1, float& o2)
{
    // magic floor: m = RD(v*32 + 2^23) -> low mantissa bits = floor(v*32)
    float mx = __fmaf_rd(r,  32.f, 8388608.f);
    float my = __fmaf_rd(g,  32.f, 8388608.f);
    float mz = __fmaf_rd(bv, 32.f, 8388608.f);
    int ix = (int)(__float_as_uint(mx) & 0xFFu);
    int iy = (int)(__float_as_uint(my) & 0xFFu);
    int iz = (int)(__float_as_uint(mz) & 0xFFu);
    float fx = __fmaf_rn(r,  32.f, 8388608.f - mx);
    float fy = __fmaf_rn(g,  32.f, 8388608.f - my);
    float fz = __fmaf_rn(bv, 32.f, 8388608.f - mz);
    int base = (ix*33 + iy)*33 + iz;
    float wx0 = 1.f - fx, wy0 = 1.f - fy, wz0 = 1.f - fz;
    float a00 = wx0*wy0, a01 = wx0*fy, a10 = fx*wy0, a11 = fx*fy;
    float w[8] = { a00*wz0, a00*fz, a01*wz0, a01*fz,
                   a10*wz0, a10*fz, a11*wz0, a11*fz };
    const int off[8] = {0, 1, 33, 34, 1089, 1090, 1122, 1123};
    float s0 = 0.f, s1 = 0.f, s2 = 0.f;
    #pragma unroll
    for (int j = 0; j < 8; j++) {
        unsigned int q = sm[base + off[j]];
        float fr = __uint_as_float(0x4B000000u | (q >> 21));
        float fg = __uint_as_float(0x4B000000u | ((q >> 10) & 0x7FFu));
        float fb = __uint_as_float(0x4B000000u | (q & 0x3FFu));
        s0 = fmaf(w[j], fr, s0);
        s1 = fmaf(w[j], fg, s1);
        s2 = fmaf(w[j], fb, s2);
    }
    // out = l' + s*step + A*v   (A*v == (A/32)*(v*32), exact)
    o0 = fmaf(s0, qp.s0, qp.l0) + qp.A * r;
    o1 = fmaf(s1, qp.s1, qp.l1) + qp.A * g;
    o2 = fmaf(s2, qp.s2, qp.l2) + qp.A * bv;
}

__global__ void __launch_bounds__(1024, 1) trilerp_kernel(
    const float* __restrict__ img, float* __restrict__ d_out)
{
    extern __shared__ __align__(16) unsigned int sm[];
    int b  = blockIdx.x / 37;
    int bb = blockIdx.x % 37;
    int tid = threadIdx.x;
    if (blockIdx.x == 0 && tid == 0)
        d_out[NORM_OFF] = g_norm * (1.f / (float)(NB*G3*3));

    // quant parameters (g_rmin/g_rmax finalized by delta_kernel)
    float lo0 = funmap(g_rmin[0]), hi0 = funmap(g_rmax[0]);
    float lo1 = funmap(g_rmin[1]), hi1 = funmap(g_rmax[1]);
    float lo2 = funmap(g_rmin[2]), hi2 = funmap(g_rmax[2]);
    float is0 = 2047.f / fmaxf(hi0 - lo0, 1e-20f);
    float is1 = 2047.f / fmaxf(hi1 - lo1, 1e-20f);
    float is2 = 1023.f / fmaxf(hi2 - lo2, 1e-20f);
    float A   = g_A[b];
    float a32 = A * (1.f/32.f);

    // fused quantize-while-fill of the smem LUT
    const float* Lp = d_out + L_OFF + (size_t)b*G3*3;
    for (int n = tid; n < G3; n += 1024) {
        int x = n / 1089, rem = n - x*1089;
        int y = rem / 33, z = rem - y*33;
        float r0 = Lp[n*3    ] - a32*(float)x;
        float r1 = Lp[n*3 + 1] - a32*(float)y;
        float r2 = Lp[n*3 + 2] - a32*(float)z;
        unsigned int q0 = (unsigned int)min(max((int)fmaf(r0 - lo0, is0, 0.5f), 0), 2047);
        unsigned int q1 = (unsigned int)min(max((int)fmaf(r1 - lo1, is1, 0.5f), 0), 2047);
        unsigned int q2 = (unsigned int)min(max((int)fmaf(r2 - lo2, is2, 0.5f), 0), 1023);
        sm[n] = (q0 << 21) | (q1 << 10) | q2;
    }

    QP qp;
    qp.s0 = fmaxf(hi0 - lo0, 1e-20f) * (1.f/2047.f);
    qp.s1 = fmaxf(hi1 - lo1, 1e-20f) * (1.f/2047.f);
    qp.s2 = fmaxf(hi2 - lo2, 1e-20f) * (1.f/1023.f);
    qp.l0 = lo0 - 8388608.f * qp.s0;
    qp.l1 = lo1 - 8388608.f * qp.s1;
    qp.l2 = lo2 - 8388608.f * qp.s2;
    qp.A  = A;
    __syncthreads();

    const float2* Rp = (const float2*)(img + (size_t)(b*3 + 0)*NPIX);
    const float2* Gp = (const float2*)(img + (size_t)(b*3 + 1)*NPIX);
    const float2* Bp = (const float2*)(img + (size_t)(b*3 + 2)*NPIX);
    float2* oR = (float2*)(d_out + (size_t)(b*3 + 0)*NPIX);
    float2* oG = (float2*)(d_out + (size_t)(b*3 + 1)*NPIX);
    float2* oB = (float2*)(d_out + (size_t)(b*3 + 2)*NPIX);

    const int NQ = NPIX/2;
    for (int q = bb*1024 + tid; q < NQ; q += 37*1024) {
        float2 r2 = Rp[q], g2 = Gp[q], b2 = Bp[q];
        float2 o0, o1, o2;
        lut1(r2.x, g2.x, b2.x, sm, qp, o0.x, o1.x, o2.x);
        lut1(r2.y, g2.y, b2.y, sm, qp, o0.y, o1.y, o2.y);
        oR[q] = o0; oG[q] = o1; oB[q] = o2;
    }
}

// ============================================================
// launch
// ============================================================
extern "C" void kernel_launch(void* const* d_in, const int* in_sizes, int n_in,
                              void* d_out_v, int out_size)
{
    const float* img_lr   = (const float*)d_in[0];
    const float* img_full = (const float*)d_in[1];
    const float* bases    = (const float*)d_in[2];
    const float* wp_c1_w  = (const float*)d_in[3];
    const float* wp_c1_b  = (const float*)d_in[4];
    const float* wp_c2_w  = (const float*)d_in[5];
    const float* wp_c2_b  = (const float*)d_in[6];
    const float* wp_fc_w  = (const float*)d_in[7];
    const float* wp_fc_b  = (const float*)d_in[8];
    const float* rp_c1_w  = (const float*)d_in[9];
    const float* rp_c1_b  = (const float*)d_in[10];
    const float* rp_c2_w  = (const float*)d_in[11];
    const float* rp_c2_b  = (const float*)d_in[12];
    const float* rp_fcu_w = (const float*)d_in[13];
    const float* rp_fcu_b = (const float*)d_in[14];
    const float* rp_fcv_w = (const float*)d_in[15];
    const float* rp_fcv_b = (const float*)d_in[16];
    const float* rp_fcw_w = (const float*)d_in[17];
    const float* rp_fcw_b = (const float*)d_in[18];
    const float* rp_fcc_w = (const float*)d_in[19];
    const float* rp_fcc_b = (const float*)d_in[20];
    float* d_out = (float*)d_out_v;

    cudaFuncSetAttribute(trilerp_kernel,
                         cudaFuncAttributeMaxDynamicSharedMemorySize, TRI_SMEM);

    conv1_kernel<<<512, 256>>>(img_lr, wp_c1_w, wp_c1_b, rp_c1_w, rp_c1_b);
    conv2_kernel<<<256, 256>>>(wp_c2_w, wp_c2_b, rp_c2_w, rp_c2_b);
    delta_kernel<<<(G3 + 255)/256, 256>>>(bases, d_out,
                          wp_fc_w, wp_fc_b,
                          rp_fcu_w, rp_fcu_b, rp_fcv_w, rp_fcv_b,
                          rp_fcw_w, rp_fcw_b, rp_fcc_w, rp_fcc_b);
    trilerp_kernel<<<148, 1024, TRI_SMEM>>>(img_full, d_out);
}

// round 13
// speedup vs baseline: 1.5257x; 1.5257x over previous
#include <cuda_runtime.h>
#include <cuda_fp16.h>

// ---------------- problem constants ----------------
#define GG   33
#define G3   35937            // 33^3
#define KK   8
#define RR   8
#define NB   4
#define HL   256
#define WL   256
#define HF   1080
#define WF   1920
#define NPIX (HF*WF)          // 2,073,600
#define OUT_IMG (NB*3*NPIX)   // 24,883,200

// d_out layout: out | alpha | delta | L | delta_norm  (all float32, concatenated)
#define ALPHA_OFF OUT_IMG
#define DELTA_SZ  (NB*G3*3)            // 431,244
#define DELTA_OFF (ALPHA_OFF + 32)
#define L_OFF     (DELTA_OFF + DELTA_SZ)
#define NORM_OFF  (L_OFF + DELTA_SZ)

#define TRI_SMEM (G3*4 + 16)           // packed uint32 LUT: 143.7 KB

// ---------------- device scratch (no allocations allowed) ----------------
__device__ float g_s1[2*NB*16*128*128];   // conv1 outputs, both encoders
__device__ float g_hsum[2*NB*32];
__device__ float g_alpha[NB*KK];
__device__ float g_A[NB];                 // sum_k alpha[b][k]  (ramp slope)
__device__ float g_u[NB*RR*GG];
__device__ float g_v[NB*RR*GG];
__device__ float g_w[NB*RR*GG];
__device__ float g_c[NB*RR*3];
__device__ float g_norm;
__device__ unsigned int g_rmin[3];        // mapped-uint residual min per channel
__device__ unsigned int g_rmax[3];

// monotonic float<->uint mapping for atomic min/max
__device__ __forceinline__ unsigned int fmap(float f) {
    unsigned int b = __float_as_uint(f);
    return b ^ (((unsigned int)((int)b >> 31)) | 0x80000000u);
}
__device__ __forceinline__ float funmap(unsigned int m) {
    unsigned int b = (m & 0x80000000u) ? (m ^ 0x80000000u) : ~m;
    return __uint_as_float(b);
}

// ============================================================
// K1: conv1 (3->16, 3x3, stride2, pad1) + relu, both encoders
// ============================================================
__global__ void __launch_bounds__(256) conv1_kernel(
    const float* __restrict__ img_lr,
    const float* __restrict__ w_wp, const float* __restrict__ b_wp,
    const float* __restrict__ w_rp, const float* __restrict__ b_rp)
{
    __shared__ float ws[432];
    __shared__ float bs[16];
    int blk = blockIdx.x;          // 0..511
    int e   = blk >> 8;
    int rem = blk & 255;
    int b   = rem >> 6;
    int tile= rem & 63;
    const float* w  = e ? w_rp : w_wp;
    const float* bi = e ? b_rp : b_wp;
    int tid = threadIdx.x;
    for (int i = tid; i < 432; i += 256) ws[i] = w[i];
    if (tid < 16) bs[tid] = bi[tid];
    if (blk == 0) g_hsum[tid] = 0.f;
    __syncthreads();

    int pix = tile*256 + tid;
    int oh = pix >> 7, ow = pix & 127;
    float in[27];
    #pragma unroll
    for (int ci = 0; ci < 3; ci++)
      #pragma unroll
      for (int kh = 0; kh < 3; kh++)
        #pragma unroll
        for (int kw = 0; kw < 3; kw++) {
            int ih = 2*oh - 1 + kh, iw = 2*ow - 1 + kw;
            float v = 0.f;
            if (ih >= 0 && ih < HL && iw >= 0 && iw < WL)
                v = img_lr[((b*3 + ci)*HL + ih)*WL + iw];
            in[ci*9 + kh*3 + kw] = v;
        }
    float acc[16];
    #pragma unroll
    for (int co = 0; co < 16; co++) acc[co] = bs[co];
    #pragma unroll
    for (int j = 0; j < 27; j++) {
        float v = in[j];
        #pragma unroll
        for (int co = 0; co < 16; co++) acc[co] = fmaf(v, ws[co*27 + j], acc[co]);
    }
    float* outp = g_s1 + (size_t)(e*NB + b)*16*16384 + pix;
    #pragma unroll
    for (int co = 0; co < 16; co++) outp[co*16384] = fmaxf(acc[co], 0.f);
}

// ============================================================
// K2: conv2 (16->32, 3x3, stride2, pad1) + relu + spatial-sum
// ============================================================
__global__ void __launch_bounds__(256) conv2_kernel(
    const float* __restrict__ w_wp, const float* __restrict__ b_wp,
    const float* __restrict__ w_rp, const float* __restrict__ b_rp)
{
    __shared__ float ws[2304];   // [(ci*9+k)*16 + co_local]
    __shared__ float bs[16];
    __shared__ float red[8*16];
    int blk = blockIdx.x;        // 0..255
    int e      = blk >> 7;
    int rem    = blk & 127;
    int b      = rem >> 5;
    int cohalf = (rem >> 4) & 1;
    int tile   = rem & 15;
    const float* w  = e ? w_rp : w_wp;
    const float* bi = e ? b_rp : b_wp;
    int tid = threadIdx.x;
    for (int t = tid; t < 2304; t += 256) {
        int col = t & 15;
        int cik = t >> 4;
        int ci = cik / 9, k = cik - ci*9;
        ws[t] = w[((cohalf*16 + col)*16 + ci)*9 + k];
    }
    if (tid < 16) bs[tid] = bi[cohalf*16 + tid];
    __syncthreads();

    int pix = tile*256 + tid;
    int oh = pix >> 6, ow = pix & 63;
    const float* inp = g_s1 + (size_t)(e*NB + b)*16*16384;
    float acc[16];
    #pragma unroll
    for (int co = 0; co < 16; co++) acc[co] = 0.f;
    for (int ci = 0; ci < 16; ci++) {
        float v9[9];
        #pragma unroll
        for (int kh = 0; kh < 3; kh++)
          #pragma unroll
          for (int kw = 0; kw < 3; kw++) {
              int ih = 2*oh - 1 + kh, iw = 2*ow - 1 + kw;
              float v = 0.f;
              if (ih >= 0 && ih < 128 && iw >= 0 && iw < 128)
                  v = inp[ci*16384 + ih*128 + iw];
              v9[kh*3 + kw] = v;
          }
        #pragma unroll
        for (int k = 0; k < 9; k++) {
            float v = v9[k];
            const float* wrow = &ws[(ci*9 + k)*16];
            #pragma unroll
            for (int co = 0; co < 16; co++) acc[co] = fmaf(v, wrow[co], acc[co]);
        }
    }
    int lane = tid & 31, wid = tid >> 5;
    #pragma unroll
    for (int co = 0; co < 16; co++) {
        float v = fmaxf(acc[co] + bs[co], 0.f);   // relu BEFORE mean
        v += __shfl_down_sync(0xffffffffu, v, 16);
        v += __shfl_down_sync(0xffffffffu, v, 8);
        v += __shfl_down_sync(0xffffffffu, v, 4);
        v += __shfl_down_sync(0xffffffffu, v, 2);
        v += __shfl_down_sync(0xffffffffu, v, 1);
        if (lane == 0) red[wid*16 + co] = v;
    }
    __syncthreads();
    if (tid < 16) {
        float s = 0.f;
        #pragma unroll
        for (int w8 = 0; w8 < 8; w8++) s += red[w8*16 + tid];
        atomicAdd(&g_hsum[(e*NB + b)*32 + cohalf*16 + tid], s);
    }
}

// ============================================================
// K3: FC heads + init of min/max + ramp slopes
// ============================================================
__global__ void fc_kernel(
    const float* __restrict__ wp_fc_w, const float* __restrict__ wp_fc_b,
    const float* __restrict__ fcu_w,  const float* __restrict__ fcu_b,
    const float* __restrict__ fcv_w,  const float* __restrict__ fcv_b,
    const float* __restrict__ fcw_w,  const float* __restrict__ fcw_b,
    const float* __restrict__ fcc_w,  const float* __restrict__ fcc_b,
    float* __restrict__ d_out)
{
    __shared__ float h[2*NB*32];
    __shared__ float sal[NB*KK];
    int tid = threadIdx.x;
    h[tid] = g_hsum[tid] * (1.f/4096.f);
    if (tid == 0) g_norm = 0.f;
    if (tid < 3) { g_rmin[tid] = 0xFFFFFFFFu; g_rmax[tid] = 0u; }
    __syncthreads();

    if (tid < NB*KK) {                        // alpha (wp encoder)
        int b = tid >> 3, k = tid & 7;
        float s = wp_fc_b[k];
        const float* hb = &h[b*32];
        #pragma unroll
        for (int i = 0; i < 32; i++) s = fmaf(hb[i], wp_fc_w[k*32 + i], s);
        g_alpha[tid] = s;
        sal[tid] = s;
        d_out[ALPHA_OFF + tid] = s;
    }
    __syncthreads();
    if (tid < NB) {
        float a = 0.f;
        #pragma unroll
        for (int k = 0; k < KK; k++) a += sal[tid*KK + k];
        g_A[tid] = a;
    }
    for (int j = tid; j < NB*RR*GG; j += 256) {   // u,v,w (rp encoder)
        int b = j / (RR*GG), jj = j - b*(RR*GG);
        const float* hb = &h[(NB + b)*32];
        float su = fcu_b[jj], sv = fcv_b[jj], sw = fcw_b[jj];
        #pragma unroll
        for (int i = 0; i < 32; i++) {
            float hv = hb[i];
            su = fmaf(hv, fcu_w[jj*32 + i], su);
            sv = fmaf(hv, fcv_w[jj*32 + i], sv);
            sw = fmaf(hv, fcw_w[jj*32 + i], sw);
        }
        g_u[j] = su; g_v[j] = sv; g_w[j] = sw;
    }
    for (int j = tid; j < NB*RR*3; j += 256) {    // c
        int b = j / (RR*3), jj = j - b*(RR*3);
        const float* hb = &h[(NB + b)*32];
        float s = fcc_b[jj];
        #pragma unroll
        for (int i = 0; i < 32; i++) s = fmaf(hb[i], fcc_w[jj*32 + i], s);
        g_c[j] = s;
    }
}

// ============================================================
// K4: delta + L + residual min/max. 4 batches per thread:
// bases[k][n][:] loaded ONCE and reused for all batches.
// ============================================================
__global__ void __launch_bounds__(256) delta_kernel(
    const float* __restrict__ bases, float* __restrict__ d_out)
{
    __shared__ float su[NB*RR*GG], sv[NB*RR*GG], sw[NB*RR*GG];
    __shared__ float sc[NB*RR*3];
    __shared__ float sa[NB*KK];
    __shared__ float sA[NB];
    int tid = threadIdx.x;
    for (int i = tid; i < NB*RR*GG; i += 256) {
        su[i] = g_u[i]; sv[i] = g_v[i]; sw[i] = g_w[i];
    }
    if (tid < NB*RR*3) sc[tid] = g_c[tid];
    if (tid < NB*KK)   sa[tid] = g_alpha[tid];
    if (tid < NB)      sA[tid] = g_A[tid];
    __syncthreads();

    int n = blockIdx.x*256 + tid;
    float local = 0.f;
    unsigned int mn0 = 0xFFFFFFFFu, mn1 = 0xFFFFFFFFu, mn2 = 0xFFFFFFFFu;
    unsigned int mx0 = 0u, mx1 = 0u, mx2 = 0u;
    if (n < G3) {
        int x = n / 1089, rem = n - x*1089;
        int y = rem / 33, z = rem - y*33;
        float bb[KK][3];
        #pragma unroll
        for (int k = 0; k < KK; k++) {
            const float* bp = bases + ((size_t)k*G3 + n)*3;
            bb[k][0] = bp[0]; bb[k][1] = bp[1]; bb[k][2] = bp[2];
        }
        #pragma unroll
        for (int b = 0; b < NB; b++) {
            float d0 = 0.f, d1 = 0.f, d2 = 0.f;
            #pragma unroll
            for (int r = 0; r < RR; r++) {
                int o = b*RR + r;
                float p = su[o*GG + x] * sv[o*GG + y] * sw[o*GG + z];
                d0 = fmaf(p, sc[o*3 + 0], d0);
                d1 = fmaf(p, sc[o*3 + 1], d1);
                d2 = fmaf(p, sc[o*3 + 2], d2);
            }
            float l0 = d0, l1 = d1, l2 = d2;
            #pragma unroll
            for (int k = 0; k < KK; k++) {
                float a = sa[b*KK + k];
                l0 = fmaf(a, bb[k][0], l0);
                l1 = fmaf(a, bb[k][1], l1);
                l2 = fmaf(a, bb[k][2], l2);
            }
            size_t off = (size_t)(b*G3 + n)*3;
            d_out[DELTA_OFF + off    ] = d0;
            d_out[DELTA_OFF + off + 1] = d1;
            d_out[DELTA_OFF + off + 2] = d2;
            d_out[L_OFF + off    ] = l0;
            d_out[L_OFF + off + 1] = l1;
            d_out[L_OFF + off + 2] = l2;
            local += fabsf(d0) + fabsf(d1) + fabsf(d2);
            float a32 = sA[b] * (1.f/32.f);
            unsigned int r0 = fmap(l0 - a32*(float)x);
            unsigned int r1 = fmap(l1 - a32*(float)y);
            unsigned int r2 = fmap(l2 - a32*(float)z);
            mn0 = min(mn0, r0); mx0 = max(mx0, r0);
            mn1 = min(mn1, r1); mx1 = max(mx1, r1);
            mn2 = min(mn2, r2); mx2 = max(mx2, r2);
        }
    }
    mn0 = __reduce_min_sync(0xffffffffu, mn0);
    mn1 = __reduce_min_sync(0xffffffffu, mn1);
    mn2 = __reduce_min_sync(0xffffffffu, mn2);
    mx0 = __reduce_max_sync(0xffffffffu, mx0);
    mx1 = __reduce_max_sync(0xffffffffu, mx1);
    mx2 = __reduce_max_sync(0xffffffffu, mx2);
    local += __shfl_down_sync(0xffffffffu, local, 16);
    local += __shfl_down_sync(0xffffffffu, local, 8);
    local += __shfl_down_sync(0xffffffffu, local, 4);
    local += __shfl_down_sync(0xffffffffu, local, 2);
    local += __shfl_down_sync(0xffffffffu, local, 1);
    if ((threadIdx.x & 31) == 0) {
        atomicAdd(&g_norm, local);
        atomicMin(&g_rmin[0], mn0); atomicMax(&g_rmax[0], mx0);
        atomicMin(&g_rmin[1], mn1); atomicMax(&g_rmax[1], mx1);
        atomicMin(&g_rmin[2], mn2); atomicMax(&g_rmax[2], mx2);
    }
}

// ============================================================
// K5: trilinear LUT apply. Byte-aligned packed node r:8|g:8|b:16;
// field->float via single PRMT (mantissa magic). Quantize fused
// into smem fill. Magic-number floor, 2px/iter.
// ============================================================
struct QP { float s0, s1, s2, l0, l1, l2, A; };

__device__ __forceinline__ void lut1(
    float r, float g, float bv,
    const unsigned int* __restrict__ sm, const QP& qp,
    float& o0, float& o1, float& o2)
{
    // magic floor: m = RD(v*32 + 2^23) -> low mantissa bits = floor(v*32)
    float mx = __fmaf_rd(r,  32.f, 8388608.f);
    float my = __fmaf_rd(g,  32.f, 8388608.f);
    float mz = __fmaf_rd(bv, 32.f, 8388608.f);
    int ix = (int)(__float_as_uint(mx) & 0xFFu);
    int iy = (int)(__float_as_uint(my) & 0xFFu);
    int iz = (int)(__float_as_uint(mz) & 0xFFu);
    float fx = __fmaf_rn(r,  32.f, 8388608.f - mx);
    float fy = __fmaf_rn(g,  32.f, 8388608.f - my);
    float fz = __fmaf_rn(bv, 32.f, 8388608.f - mz);
    int base = (ix*33 + iy)*33 + iz;
    float wx0 = 1.f - fx, wy0 = 1.f - fy, wz0 = 1.f - fz;
    float a00 = wx0*wy0, a01 = wx0*fy, a10 = fx*wy0, a11 = fx*fy;
    float w[8] = { a00*wz0, a00*fz, a01*wz0, a01*fz,
                   a10*wz0, a10*fz, a11*wz0, a11*fz };
    const int off[8] = {0, 1, 33, 34, 1089, 1090, 1122, 1123};
    float s0 = 0.f, s1 = 0.f, s2 = 0.f;
    #pragma unroll
    for (int j = 0; j < 8; j++) {
        unsigned int q = sm[base + off[j]];
        // one PRMT per channel: build 2^23 + field directly
        float fr = __uint_as_float(__byte_perm(q, 0x4B000000u, 0x7543)); // byte3
        float fg = __uint_as_float(__byte_perm(q, 0x4B000000u, 0x7542)); // byte2
        float fb = __uint_as_float(__byte_perm(q, 0x4B000000u, 0x7410)); // bytes1:0
        s0 = fmaf(w[j], fr, s0);
        s1 = fmaf(w[j], fg, s1);
        s2 = fmaf(w[j], fb, s2);
    }
    // out = l' + s*step + A*v   (A*v == (A/32)*(v*32), exact)
    o0 = fmaf(s0, qp.s0, qp.l0) + qp.A * r;
    o1 = fmaf(s1, qp.s1, qp.l1) + qp.A * g;
    o2 = fmaf(s2, qp.s2, qp.l2) + qp.A * bv;
}

__global__ void __launch_bounds__(1024, 1) trilerp_kernel(
    const float* __restrict__ img, float* __restrict__ d_out)
{
    extern __shared__ __align__(16) unsigned int sm[];
    int b  = blockIdx.x / 37;
    int bb = blockIdx.x % 37;
    int tid = threadIdx.x;
    if (blockIdx.x == 0 && tid == 0)
        d_out[NORM_OFF] = g_norm * (1.f / (float)(NB*G3*3));

    // quant parameters (g_rmin/g_rmax finalized by delta_kernel)
    float lo0 = funmap(g_rmin[0]), hi0 = funmap(g_rmax[0]);
    float lo1 = funmap(g_rmin[1]), hi1 = funmap(g_rmax[1]);
    float lo2 = funmap(g_rmin[2]), hi2 = funmap(g_rmax[2]);
    float is0 = 255.f   / fmaxf(hi0 - lo0, 1e-20f);
    float is1 = 255.f   / fmaxf(hi1 - lo1, 1e-20f);
    float is2 = 65535.f / fmaxf(hi2 - lo2, 1e-20f);
    float A   = g_A[b];
    float a32 = A * (1.f/32.f);

    // fused quantize-while-fill: node = r:8@byte3 | g:8@byte2 | b:16@bytes1:0
    const float* Lp = d_out + L_OFF + (size_t)b*G3*3;
    for (int n = tid; n < G3; n += 1024) {
        int x = n / 1089, rem = n - x*1089;
        int y = rem / 33, z = rem - y*33;
        float r0 = Lp[n*3    ] - a32*(float)x;
        float r1 = Lp[n*3 + 1] - a32*(float)y;
        float r2 = Lp[n*3 + 2] - a32*(float)z;
        unsigned int q0 = (unsigned int)min(max((int)fmaf(r0 - lo0, is0, 0.5f), 0), 255);
        unsigned int q1 = (unsigned int)min(max((int)fmaf(r1 - lo1, is1, 0.5f), 0), 255);
        unsigned int q2 = (unsigned int)min(max((int)fmaf(r2 - lo2, is2, 0.5f), 0), 65535);
        sm[n] = (q0 << 24) | (q1 << 16) | q2;
    }

    QP qp;
    qp.s0 = fmaxf(hi0 - lo0, 1e-20f) * (1.f/255.f);
    qp.s1 = fmaxf(hi1 - lo1, 1e-20f) * (1.f/255.f);
    qp.s2 = fmaxf(hi2 - lo2, 1e-20f) * (1.f/65535.f);
    qp.l0 = lo0 - 8388608.f * qp.s0;
    qp.l1 = lo1 - 8388608.f * qp.s1;
    qp.l2 = lo2 - 8388608.f * qp.s2;
    qp.A  = A;
    __syncthreads();

    const float2* Rp = (const float2*)(img + (size_t)(b*3 + 0)*NPIX);
    const float2* Gp = (const float2*)(img + (size_t)(b*3 + 1)*NPIX);
    const float2* Bp = (const float2*)(img + (size_t)(b*3 + 2)*NPIX);
    float2* oR = (float2*)(d_out + (size_t)(b*3 + 0)*NPIX);
    float2* oG = (float2*)(d_out + (size_t)(b*3 + 1)*NPIX);
    float2* oB = (float2*)(d_out + (size_t)(b*3 + 2)*NPIX);

    const int NQ = NPIX/2;
    for (int q = bb*1024 + tid; q < NQ; q += 37*1024) {
        float2 r2 = Rp[q], g2 = Gp[q], b2 = Bp[q];
        float2 o0, o1, o2;
        lut1(r2.x, g2.x, b2.x, sm, qp, o0.x, o1.x, o2.x);
        lut1(r2.y, g2.y, b2.y, sm, qp, o0.y, o1.y, o2.y);
        oR[q] = o0; oG[q] = o1; oB[q] = o2;
    }
}

// ============================================================
// launch
// ============================================================
extern "C" void kernel_launch(void* const* d_in, const int* in_sizes, int n_in,
                              void* d_out_v, int out_size)
{
    const float* img_lr   = (const float*)d_in[0];
    const float* img_full = (const float*)d_in[1];
    const float* bases    = (const float*)d_in[2];
    const float* wp_c1_w  = (const float*)d_in[3];
    const float* wp_c1_b  = (const float*)d_in[4];
    const float* wp_c2_w  = (const float*)d_in[5];
    const float* wp_c2_b  = (const float*)d_in[6];
    const float* wp_fc_w  = (const float*)d_in[7];
    const float* wp_fc_b  = (const float*)d_in[8];
    const float* rp_c1_w  = (const float*)d_in[9];
    const float* rp_c1_b  = (const float*)d_in[10];
    const float* rp_c2_w  = (const float*)d_in[11];
    const float* rp_c2_b  = (const float*)d_in[12];
    const float* rp_fcu_w = (const float*)d_in[13];
    const float* rp_fcu_b = (const float*)d_in[14];
    const float* rp_fcv_w = (const float*)d_in[15];
    const float* rp_fcv_b = (const float*)d_in[16];
    const float* rp_fcw_w = (const float*)d_in[17];
    const float* rp_fcw_b = (const float*)d_in[18];
    const float* rp_fcc_w = (const float*)d_in[19];
    const float* rp_fcc_b = (const float*)d_in[20];
    float* d_out = (float*)d_out_v;

    cudaFuncSetAttribute(trilerp_kernel,
                         cudaFuncAttributeMaxDynamicSharedMemorySize, TRI_SMEM);

    conv1_kernel<<<512, 256>>>(img_lr, wp_c1_w, wp_c1_b, rp_c1_w, rp_c1_b);
    conv2_kernel<<<256, 256>>>(wp_c2_w, wp_c2_b, rp_c2_w, rp_c2_b);
    fc_kernel<<<1, 256>>>(wp_fc_w, wp_fc_b,
                          rp_fcu_w, rp_fcu_b, rp_fcv_w, rp_fcv_b,
                          rp_fcw_w, rp_fcw_b, rp_fcc_w, rp_fcc_b, d_out);
    delta_kernel<<<(G3 + 255)/256, 256>>>(bases, d_out);
    trilerp_kernel<<<148, 1024, TRI_SMEM>>>(img_full, d_out);
}

// round 14
// speedup vs baseline: 1.5315x; 1.0038x over previous
#include <cuda_runtime.h>
#include <cuda_fp16.h>

// ---------------- problem constants ----------------
#define GG   33
#define G3   35937            // 33^3
#define KK   8
#define RR   8
#define NB   4
#define HL   256
#define WL   256
#define HF   1080
#define WF   1920
#define NPIX (HF*WF)          // 2,073,600
#define OUT_IMG (NB*3*NPIX)   // 24,883,200

// d_out layout: out | alpha | delta | L | delta_norm  (all float32, concatenated)
#define ALPHA_OFF OUT_IMG
#define DELTA_SZ  (NB*G3*3)            // 431,244
#define DELTA_OFF (ALPHA_OFF + 32)
#define L_OFF     (DELTA_OFF + DELTA_SZ)
#define NORM_OFF  (L_OFF + DELTA_SZ)

#define TRI_SMEM (G3*4 + 16)           // packed uint32 LUT: 143.7 KB

// ---------------- device scratch (no allocations allowed) ----------------
__device__ float g_s1[2*NB*16*128*128];   // conv1 outputs, both encoders
__device__ float g_hsum[2*NB*32];
__device__ float g_alpha[NB*KK];
__device__ float g_A[NB];                 // sum_k alpha[b][k]  (ramp slope)
__device__ float g_u[NB*RR*GG];
__device__ float g_v[NB*RR*GG];
__device__ float g_w[NB*RR*GG];
__device__ float g_c[NB*RR*3];
__device__ float g_norm;
__device__ unsigned int g_rmin[3];        // mapped-uint residual min per channel
__device__ unsigned int g_rmax[3];
__device__ unsigned int g_ticket;         // conv2 last-block counter

// monotonic float<->uint mapping for atomic min/max
__device__ __forceinline__ unsigned int fmap(float f) {
    unsigned int b = __float_as_uint(f);
    return b ^ (((unsigned int)((int)b >> 31)) | 0x80000000u);
}
__device__ __forceinline__ float funmap(unsigned int m) {
    unsigned int b = (m & 0x80000000u) ? (m ^ 0x80000000u) : ~m;
    return __uint_as_float(b);
}

// ============================================================
// K1: conv1 (3->16, 3x3, stride2, pad1) + relu, both encoders
// blk 0 also initializes global reduction scalars (stream-ordered
// before conv2 which consumes them).
// ============================================================
__global__ void __launch_bounds__(256) conv1_kernel(
    const float* __restrict__ img_lr,
    const float* __restrict__ w_wp, const float* __restrict__ b_wp,
    const float* __restrict__ w_rp, const float* __restrict__ b_rp)
{
    __shared__ float ws[432];
    __shared__ float bs[16];
    int blk = blockIdx.x;          // 0..511
    int e   = blk >> 8;
    int rem = blk & 255;
    int b   = rem >> 6;
    int tile= rem & 63;
    const float* w  = e ? w_rp : w_wp;
    const float* bi = e ? b_rp : b_wp;
    int tid = threadIdx.x;
    for (int i = tid; i < 432; i += 256) ws[i] = w[i];
    if (tid < 16) bs[tid] = bi[tid];
    if (blk == 0) {
        g_hsum[tid] = 0.f;
        if (tid == 0) { g_norm = 0.f; g_ticket = 0u; }
        if (tid < 3) { g_rmin[tid] = 0xFFFFFFFFu; g_rmax[tid] = 0u; }
    }
    __syncthreads();

    int pix = tile*256 + tid;
    int oh = pix >> 7, ow = pix & 127;
    float in[27];
    #pragma unroll
    for (int ci = 0; ci < 3; ci++)
      #pragma unroll
      for (int kh = 0; kh < 3; kh++)
        #pragma unroll
        for (int kw = 0; kw < 3; kw++) {
            int ih = 2*oh - 1 + kh, iw = 2*ow - 1 + kw;
            float v = 0.f;
            if (ih >= 0 && ih < HL && iw >= 0 && iw < WL)
                v = img_lr[((b*3 + ci)*HL + ih)*WL + iw];
            in[ci*9 + kh*3 + kw] = v;
        }
    float acc[16];
    #pragma unroll
    for (int co = 0; co < 16; co++) acc[co] = bs[co];
    #pragma unroll
    for (int j = 0; j < 27; j++) {
        float v = in[j];
        #pragma unroll
        for (int co = 0; co < 16; co++) acc[co] = fmaf(v, ws[co*27 + j], acc[co]);
    }
    float* outp = g_s1 + (size_t)(e*NB + b)*16*16384 + pix;
    #pragma unroll
    for (int co = 0; co < 16; co++) outp[co*16384] = fmaxf(acc[co], 0.f);
}

// ============================================================
// K2: conv2 (16->32, 3x3, stride2, pad1) + relu + spatial-sum.
// The block that retires the LAST ticket also computes the FC heads
// (fc_kernel folded in; saves a launch).
// ============================================================
__global__ void __launch_bounds__(256) conv2_kernel(
    const float* __restrict__ w_wp, const float* __restrict__ b_wp,
    const float* __restrict__ w_rp, const float* __restrict__ b_rp,
    const float* __restrict__ wp_fc_w, const float* __restrict__ wp_fc_b,
    const float* __restrict__ fcu_w,  const float* __restrict__ fcu_b,
    const float* __restrict__ fcv_w,  const float* __restrict__ fcv_b,
    const float* __restrict__ fcw_w,  const float* __restrict__ fcw_b,
    const float* __restrict__ fcc_w,  const float* __restrict__ fcc_b,
    float* __restrict__ d_out)
{
    __shared__ float ws[2304];   // [(ci*9+k)*16 + co_local]
    __shared__ float bs[16];
    __shared__ float red[8*16];
    __shared__ int slast;
    int blk = blockIdx.x;        // 0..255
    int e      = blk >> 7;
    int rem    = blk & 127;
    int b      = rem >> 5;
    int cohalf = (rem >> 4) & 1;
    int tile   = rem & 15;
    const float* w  = e ? w_rp : w_wp;
    const float* bi = e ? b_rp : b_wp;
    int tid = threadIdx.x;
    for (int t = tid; t < 2304; t += 256) {
        int col = t & 15;
        int cik = t >> 4;
        int ci = cik / 9, k = cik - ci*9;
        ws[t] = w[((cohalf*16 + col)*16 + ci)*9 + k];
    }
    if (tid < 16) bs[tid] = bi[cohalf*16 + tid];
    __syncthreads();

    int pix = tile*256 + tid;
    int oh = pix >> 6, ow = pix & 63;
    const float* inp = g_s1 + (size_t)(e*NB + b)*16*16384;
    float acc[16];
    #pragma unroll
    for (int co = 0; co < 16; co++) acc[co] = 0.f;
    for (int ci = 0; ci < 16; ci++) {
        float v9[9];
        #pragma unroll
        for (int kh = 0; kh < 3; kh++)
          #pragma unroll
          for (int kw = 0; kw < 3; kw++) {
              int ih = 2*oh - 1 + kh, iw = 2*ow - 1 + kw;
              float v = 0.f;
              if (ih >= 0 && ih < 128 && iw >= 0 && iw < 128)
                  v = inp[ci*16384 + ih*128 + iw];
              v9[kh*3 + kw] = v;
          }
        #pragma unroll
        for (int k = 0; k < 9; k++) {
            float v = v9[k];
            const float* wrow = &ws[(ci*9 + k)*16];
            #pragma unroll
            for (int co = 0; co < 16; co++) acc[co] = fmaf(v, wrow[co], acc[co]);
        }
    }
    int lane = tid & 31, wid = tid >> 5;
    #pragma unroll
    for (int co = 0; co < 16; co++) {
        float v = fmaxf(acc[co] + bs[co], 0.f);   // relu BEFORE mean
        v += __shfl_down_sync(0xffffffffu, v, 16);
        v += __shfl_down_sync(0xffffffffu, v, 8);
        v += __shfl_down_sync(0xffffffffu, v, 4);
        v += __shfl_down_sync(0xffffffffu, v, 2);
        v += __shfl_down_sync(0xffffffffu, v, 1);
        if (lane == 0) red[wid*16 + co] = v;
    }
    __syncthreads();
    if (tid < 16) {
        float s = 0.f;
        #pragma unroll
        for (int w8 = 0; w8 < 8; w8++) s += red[w8*16 + tid];
        atomicAdd(&g_hsum[(e*NB + b)*32 + cohalf*16 + tid], s);
    }

    // ---- last-block FC heads ----
    __threadfence();
    if (tid == 0) slast = (atomicAdd(&g_ticket, 1u) == (unsigned)(gridDim.x - 1));
    __syncthreads();
    if (!slast) return;

    __shared__ float h[2*NB*32];
    __shared__ float sal[NB*KK];
    h[tid] = g_hsum[tid] * (1.f/4096.f);      // mean over 64x64
    __syncthreads();

    if (tid < NB*KK) {                        // alpha (wp encoder)
        int bb2 = tid >> 3, k = tid & 7;
        float s = wp_fc_b[k];
        const float* hb = &h[bb2*32];
        #pragma unroll
        for (int i = 0; i < 32; i++) s = fmaf(hb[i], wp_fc_w[k*32 + i], s);
        g_alpha[tid] = s;
        sal[tid] = s;
        d_out[ALPHA_OFF + tid] = s;
    }
    __syncthreads();
    if (tid < NB) {
        float a = 0.f;
        #pragma unroll
        for (int k = 0; k < KK; k++) a += sal[tid*KK + k];
        g_A[tid] = a;
    }
    for (int j = tid; j < NB*RR*GG; j += 256) {   // u,v,w (rp encoder)
        int bb2 = j / (RR*GG), jj = j - bb2*(RR*GG);
        const float* hb = &h[(NB + bb2)*32];
        float su = fcu_b[jj], sv = fcv_b[jj], sw = fcw_b[jj];
        #pragma unroll
        for (int i = 0; i < 32; i++) {
            float hv = hb[i];
            su = fmaf(hv, fcu_w[jj*32 + i], su);
            sv = fmaf(hv, fcv_w[jj*32 + i], sv);
            sw = fmaf(hv, fcw_w[jj*32 + i], sw);
        }
        g_u[j] = su; g_v[j] = sv; g_w[j] = sw;
    }
    for (int j = tid; j < NB*RR*3; j += 256) {    // c
        int bb2 = j / (RR*3), jj = j - bb2*(RR*3);
        const float* hb = &h[(NB + bb2)*32];
        float s = fcc_b[jj];
        #pragma unroll
        for (int i = 0; i < 32; i++) s = fmaf(hb[i], fcc_w[jj*32 + i], s);
        g_c[j] = s;
    }
}

// ============================================================
// K3: delta + L + residual min/max. 4 batches per thread:
// bases[k][n][:] loaded ONCE and reused for all batches.
// ============================================================
__global__ void __launch_bounds__(256) delta_kernel(
    const float* __restrict__ bases, float* __restrict__ d_out)
{
    __shared__ float su[NB*RR*GG], sv[NB*RR*GG], sw[NB*RR*GG];
    __shared__ float sc[NB*RR*3];
    __shared__ float sa[NB*KK];
    __shared__ float sA[NB];
    int tid = threadIdx.x;
    for (int i = tid; i < NB*RR*GG; i += 256) {
        su[i] = g_u[i]; sv[i] = g_v[i]; sw[i] = g_w[i];
    }
    if (tid < NB*RR*3) sc[tid] = g_c[tid];
    if (tid < NB*KK)   sa[tid] = g_alpha[tid];
    if (tid < NB)      sA[tid] = g_A[tid];
    __syncthreads();

    int n = blockIdx.x*256 + tid;
    float local = 0.f;
    unsigned int mn0 = 0xFFFFFFFFu, mn1 = 0xFFFFFFFFu, mn2 = 0xFFFFFFFFu;
    unsigned int mx0 = 0u, mx1 = 0u, mx2 = 0u;
    if (n < G3) {
        int x = n / 1089, rem = n - x*1089;
        int y = rem / 33, z = rem - y*33;
        float bb[KK][3];
        #pragma unroll
        for (int k = 0; k < KK; k++) {
            const float* bp = bases + ((size_t)k*G3 + n)*3;
            bb[k][0] = bp[0]; bb[k][1] = bp[1]; bb[k][2] = bp[2];
        }
        #pragma unroll
        for (int b = 0; b < NB; b++) {
            float d0 = 0.f, d1 = 0.f, d2 = 0.f;
            #pragma unroll
            for (int r = 0; r < RR; r++) {
                int o = b*RR + r;
                float p = su[o*GG + x] * sv[o*GG + y] * sw[o*GG + z];
                d0 = fmaf(p, sc[o*3 + 0], d0);
                d1 = fmaf(p, sc[o*3 + 1], d1);
                d2 = fmaf(p, sc[o*3 + 2], d2);
            }
            float l0 = d0, l1 = d1, l2 = d2;
            #pragma unroll
            for (int k = 0; k < KK; k++) {
                float a = sa[b*KK + k];
                l0 = fmaf(a, bb[k][0], l0);
                l1 = fmaf(a, bb[k][1], l1);
                l2 = fmaf(a, bb[k][2], l2);
            }
            size_t off = (size_t)(b*G3 + n)*3;
            d_out[DELTA_OFF + off    ] = d0;
            d_out[DELTA_OFF + off + 1] = d1;
            d_out[DELTA_OFF + off + 2] = d2;
            d_out[L_OFF + off    ] = l0;
            d_out[L_OFF + off + 1] = l1;
            d_out[L_OFF + off + 2] = l2;
            local += fabsf(d0) + fabsf(d1) + fabsf(d2);
            float a32 = sA[b] * (1.f/32.f);
            unsigned int r0 = fmap(l0 - a32*(float)x);
            unsigned int r1 = fmap(l1 - a32*(float)y);
            unsigned int r2 = fmap(l2 - a32*(float)z);
            mn0 = min(mn0, r0); mx0 = max(mx0, r0);
            mn1 = min(mn1, r1); mx1 = max(mx1, r1);
            mn2 = min(mn2, r2); mx2 = max(mx2, r2);
        }
    }
    mn0 = __reduce_min_sync(0xffffffffu, mn0);
    mn1 = __reduce_min_sync(0xffffffffu, mn1);
    mn2 = __reduce_min_sync(0xffffffffu, mn2);
    mx0 = __reduce_max_sync(0xffffffffu, mx0);
    mx1 = __reduce_max_sync(0xffffffffu, mx1);
    mx2 = __reduce_max_sync(0xffffffffu, mx2);
    local += __shfl_down_sync(0xffffffffu, local, 16);
    local += __shfl_down_sync(0xffffffffu, local, 8);
    local += __shfl_down_sync(0xffffffffu, local, 4);
    local += __shfl_down_sync(0xffffffffu, local, 2);
    local += __shfl_down_sync(0xffffffffu, local, 1);
    if ((threadIdx.x & 31) == 0) {
        atomicAdd(&g_norm, local);
        atomicMin(&g_rmin[0], mn0); atomicMax(&g_rmax[0], mx0);
        atomicMin(&g_rmin[1], mn1); atomicMax(&g_rmax[1], mx1);
        atomicMin(&g_rmin[2], mn2); atomicMax(&g_rmax[2], mx2);
    }
}

// ============================================================
// K4: trilinear LUT apply. Byte-aligned packed node r:8|g:8|b:16;
// field->float via single PRMT (mantissa magic). Quantize fused
// into smem fill. Magic-number floor, 4px/iter (float4 I/O).
// ============================================================
struct QP { float s0, s1, s2, l0, l1, l2, A; };

__device__ __forceinline__ void lut1(
    float r, float g, float bv,
    const unsigned int* __restrict__ sm, const QP& qp,
    float& o0, float& o1, float& o2)
{
    // magic floor: m = RD(v*32 + 2^23) -> low mantissa bits = floor(v*32)
    float mx = __fmaf_rd(r,  32.f, 8388608.f);
    float my = __fmaf_rd(g,  32.f, 8388608.f);
    float mz = __fmaf_rd(bv, 32.f, 8388608.f);
    int ix = (int)(__float_as_uint(mx) & 0xFFu);
    int iy = (int)(__float_as_uint(my) & 0xFFu);
    int iz = (int)(__float_as_uint(mz) & 0xFFu);
    float fx = __fmaf_rn(r,  32.f, 8388608.f - mx);
    float fy = __fmaf_rn(g,  32.f, 8388608.f - my);
    float fz = __fmaf_rn(bv, 32.f, 8388608.f - mz);
    int base = (ix*33 + iy)*33 + iz;
    float wx0 = 1.f - fx, wy0 = 1.f - fy, wz0 = 1.f - fz;
    float a00 = wx0*wy0, a01 = wx0*fy, a10 = fx*wy0, a11 = fx*fy;
    float w[8] = { a00*wz0, a00*fz, a01*wz0, a01*fz,
                   a10*wz0, a10*fz, a11*wz0, a11*fz };
    const int off[8] = {0, 1, 33, 34, 1089, 1090, 1122, 1123};
    float s0 = 0.f, s1 = 0.f, s2 = 0.f;
    #pragma unroll
    for (int j = 0; j < 8; j++) {
        unsigned int q = sm[base + off[j]];
        // one PRMT per channel: build 2^23 + field directly
        float fr = __uint_as_float(__byte_perm(q, 0x4B000000u, 0x7543)); // byte3
        float fg = __uint_as_float(__byte_perm(q, 0x4B000000u, 0x7542)); // byte2
        float fb = __uint_as_float(__byte_perm(q, 0x4B000000u, 0x7410)); // bytes1:0
        s0 = fmaf(w[j], fr, s0);
        s1 = fmaf(w[j], fg, s1);
        s2 = fmaf(w[j], fb, s2);
    }
    // out = l' + s*step + A*v   (A*v == (A/32)*(v*32), exact)
    o0 = fmaf(s0, qp.s0, qp.l0) + qp.A * r;
    o1 = fmaf(s1, qp.s1, qp.l1) + qp.A * g;
    o2 = fmaf(s2, qp.s2, qp.l2) + qp.A * bv;
}

__global__ void __launch_bounds__(1024, 1) trilerp_kernel(
    const float* __restrict__ img, float* __restrict__ d_out)
{
    extern __shared__ __align__(16) unsigned int sm[];
    int b  = blockIdx.x / 37;
    int bb = blockIdx.x % 37;
    int tid = threadIdx.x;
    if (blockIdx.x == 0 && tid == 0)
        d_out[NORM_OFF] = g_norm * (1.f / (float)(NB*G3*3));

    // quant parameters (g_rmin/g_rmax finalized by delta_kernel)
    float lo0 = funmap(g_rmin[0]), hi0 = funmap(g_rmax[0]);
    float lo1 = funmap(g_rmin[1]), hi1 = funmap(g_rmax[1]);
    float lo2 = funmap(g_rmin[2]), hi2 = funmap(g_rmax[2]);
    float is0 = 255.f   / fmaxf(hi0 - lo0, 1e-20f);
    float is1 = 255.f   / fmaxf(hi1 - lo1, 1e-20f);
    float is2 = 65535.f / fmaxf(hi2 - lo2, 1e-20f);
    float A   = g_A[b];
    float a32 = A * (1.f/32.f);

    // fused quantize-while-fill: node = r:8@byte3 | g:8@byte2 | b:16@bytes1:0
    const float* Lp = d_out + L_OFF + (size_t)b*G3*3;
    for (int n = tid; n < G3; n += 1024) {
        int x = n / 1089, rem = n - x*1089;
        int y = rem / 33, z = rem - y*33;
        float r0 = Lp[n*3    ] - a32*(float)x;
        float r1 = Lp[n*3 + 1] - a32*(float)y;
        float r2 = Lp[n*3 + 2] - a32*(float)z;
        unsigned int q0 = (unsigned int)min(max((int)fmaf(r0 - lo0, is0, 0.5f), 0), 255);
        unsigned int q1 = (unsigned int)min(max((int)fmaf(r1 - lo1, is1, 0.5f), 0), 255);
        unsigned int q2 = (unsigned int)min(max((int)fmaf(r2 - lo2, is2, 0.5f), 0), 65535);
        sm[n] = (q0 << 24) | (q1 << 16) | q2;
    }

    QP qp;
    qp.s0 = fmaxf(hi0 - lo0, 1e-20f) * (1.f/255.f);
    qp.s1 = fmaxf(hi1 - lo1, 1e-20f) * (1.f/255.f);
    qp.s2 = fmaxf(hi2 - lo2, 1e-20f) * (1.f/65535.f);
    qp.l0 = lo0 - 8388608.f * qp.s0;
    qp.l1 = lo1 - 8388608.f * qp.s1;
    qp.l2 = lo2 - 8388608.f * qp.s2;
    qp.A  = A;
    __syncthreads();

    const float4* Rp = (const float4*)(img + (size_t)(b*3 + 0)*NPIX);
    const float4* Gp = (const float4*)(img + (size_t)(b*3 + 1)*NPIX);
    const float4* Bp = (const float4*)(img + (size_t)(b*3 + 2)*NPIX);
    float4* oR = (float4*)(d_out + (size_t)(b*3 + 0)*NPIX);
    float4* oG = (float4*)(d_out + (size_t)(b*3 + 1)*NPIX);
    float4* oB = (float4*)(d_out + (size_t)(b*3 + 2)*NPIX);

    const int NQ = NPIX/4;
    for (int q = bb*1024 + tid; q < NQ; q += 37*1024) {
        float4 r4 = Rp[q], g4 = Gp[q], b4 = Bp[q];
        float4 o0, o1, o2;
        lut1(r4.x, g4.x, b4.x, sm, qp, o0.x, o1.x, o2.x);
        lut1(r4.y, g4.y, b4.y, sm, qp, o0.y, o1.y, o2.y);
        lut1(r4.z, g4.z, b4.z, sm, qp, o0.z, o1.z, o2.z);
        lut1(r4.w, g4.w, b4.w, sm, qp, o0.w, o1.w, o2.w);
        oR[q] = o0; oG[q] = o1; oB[q] = o2;
    }
}

// ============================================================
// launch
// ============================================================
extern "C" void kernel_launch(void* const* d_in, const int* in_sizes, int n_in,
                              void* d_out_v, int out_size)
{
    const float* img_lr   = (const float*)d_in[0];
    const float* img_full = (const float*)d_in[1];
    const float* bases    = (const float*)d_in[2];
    const float* wp_c1_w  = (const float*)d_in[3];
    const float* wp_c1_b  = (const float*)d_in[4];
    const float* wp_c2_w  = (const float*)d_in[5];
    const float* wp_c2_b  = (const float*)d_in[6];
    const float* wp_fc_w  = (const float*)d_in[7];
    const float* wp_fc_b  = (const float*)d_in[8];
    const float* rp_c1_w  = (const float*)d_in[9];
    const float* rp_c1_b  = (const float*)d_in[10];
    const float* rp_c2_w  = (const float*)d_in[11];
    const float* rp_c2_b  = (const float*)d_in[12];
    const float* rp_fcu_w = (const float*)d_in[13];
    const float* rp_fcu_b = (const float*)d_in[14];
    const float* rp_fcv_w = (const float*)d_in[15];
    const float* rp_fcv_b = (const float*)d_in[16];
    const float* rp_fcw_w = (const float*)d_in[17];
    const float* rp_fcw_b = (const float*)d_in[18];
    const float* rp_fcc_w = (const float*)d_in[19];
    const float* rp_fcc_b = (const float*)d_in[20];
    float* d_out = (float*)d_out_v;

    cudaFuncSetAttribute(trilerp_kernel,
                         cudaFuncAttributeMaxDynamicSharedMemorySize, TRI_SMEM);

    conv1_kernel<<<512, 256>>>(img_lr, wp_c1_w, wp_c1_b, rp_c1_w, rp_c1_b);
    conv2_kernel<<<256, 256>>>(wp_c2_w, wp_c2_b, rp_c2_w, rp_c2_b,
                               wp_fc_w, wp_fc_b,
                               rp_fcu_w, rp_fcu_b, rp_fcv_w, rp_fcv_b,
                               rp_fcw_w, rp_fcw_b, rp_fcc_w, rp_fcc_b, d_out);
    delta_kernel<<<(G3 + 255)/256, 256>>>(bases, d_out);
    trilerp_kernel<<<148, 1024, TRI_SMEM>>>(img_full, d_out);
}